// round 8
// baseline (speedup 1.0000x reference)
#include <cuda_runtime.h>
#include <cuda_bf16.h>

#define NN 1024
#define HH 16
#define DD 64
#define MM 64
#define NB (NN * HH)          // 16384 independent (n,h) pairs

static constexpr float MU_C  = 0.9f;
static constexpr float EPS_C = 1e-6f;

__device__ __forceinline__ float elu1(float x) {
    return (x > 0.f) ? (x + 1.f) : __expf(x);
}

// 2 pairs per CTA, 128 threads, 16-deep front-batched loads per pair.
// pair1's loads are issued BEFORE pair0's epilogue, so the CTA's load stream
// is continuous across the pair boundary (register-neutral: pair0's data regs
// die exactly when pair1's loads issue).
// Thread t: column group g = t & 15 (m = 4g..4g+3), row-octet drow8 = t >> 4.
__global__ __launch_bounds__(128, 5)
void rma_kernel(const float* __restrict__ q_in,
                const float* __restrict__ k_in,
                const float* __restrict__ v_in,
                const float* __restrict__ Si_in,
                const float* __restrict__ Zi_in,
                const float* __restrict__ Pi_in,
                float* __restrict__ Vout,
                float* __restrict__ Sout,
                float* __restrict__ Zout,
                float* __restrict__ Pout)
{
    const int t  = threadIdx.x;        // 0..127
    const int b0 = blockIdx.x * 2;
    const int b1 = b0 + 1;

    __shared__ float  sQ[2][DD];
    __shared__ float  sK[2][DD];
    __shared__ float  sVal[2][MM];
    __shared__ float  sDot[2][2];
    __shared__ float  sZ[2];
    __shared__ float4 sAcc[2][128];

    const int base64_0   = b0 * 64;
    const int base64_1   = b1 * 64;
    const int base4096_0 = b0 * 4096;
    const int base4096_1 = b1 * 4096;

    const int g     = t & 15;
    const int drow8 = t >> 4;          // 0..7
    const int ob    = drow8 * 16 + g;  // row it adds 128 float4

    const float4* __restrict__ Pi4_0 = (const float4*)(Pi_in + base4096_0);
    const float4* __restrict__ Si4_0 = (const float4*)(Si_in + base4096_0);
    const float4* __restrict__ Pi4_1 = (const float4*)(Pi_in + base4096_1);
    const float4* __restrict__ Si4_1 = (const float4*)(Si_in + base4096_1);
    float4* __restrict__ Po4_0 = (float4*)(Pout + base4096_0);
    float4* __restrict__ So4_0 = (float4*)(Sout + base4096_0);
    float4* __restrict__ Po4_1 = (float4*)(Pout + base4096_1);
    float4* __restrict__ So4_1 = (float4*)(Sout + base4096_1);

    // ---- pair0: 16 front-batched loads ----
    float4 p0 = __ldcs(Pi4_0 + ob + 0 * 128);
    float4 p1 = __ldcs(Pi4_0 + ob + 1 * 128);
    float4 p2 = __ldcs(Pi4_0 + ob + 2 * 128);
    float4 p3 = __ldcs(Pi4_0 + ob + 3 * 128);
    float4 p4 = __ldcs(Pi4_0 + ob + 4 * 128);
    float4 p5 = __ldcs(Pi4_0 + ob + 5 * 128);
    float4 p6 = __ldcs(Pi4_0 + ob + 6 * 128);
    float4 p7 = __ldcs(Pi4_0 + ob + 7 * 128);
    float4 s0 = __ldcs(Si4_0 + ob + 0 * 128);
    float4 s1 = __ldcs(Si4_0 + ob + 1 * 128);
    float4 s2 = __ldcs(Si4_0 + ob + 2 * 128);
    float4 s3 = __ldcs(Si4_0 + ob + 3 * 128);
    float4 s4 = __ldcs(Si4_0 + ob + 4 * 128);
    float4 s5 = __ldcs(Si4_0 + ob + 5 * 128);
    float4 s6 = __ldcs(Si4_0 + ob + 6 * 128);
    float4 s7 = __ldcs(Si4_0 + ob + 7 * 128);

    // ---- small vectors for BOTH pairs (overlaps pair0 loads) ----
    {
        const int pr   = t >> 6;               // 0 or 1
        const int e    = t & 63;
        const int base = pr ? base64_1 : base64_0;

        float fq = elu1(q_in[base + e]);
        float fk = elu1(k_in[base + e]);
        sQ[pr][e] = fq;
        sK[pr][e] = fk;

        float zn = Zi_in[base + e] + fk;
        Zout[base + e] = zn;

        float d = fq * zn;
        #pragma unroll
        for (int off = 16; off > 0; off >>= 1)
            d += __shfl_down_sync(0xffffffffu, d, off);
        if ((t & 31) == 0) sDot[pr][(e >> 5) & 1] = d;

        sVal[pr][e] = v_in[base + e];
    }
    __syncthreads();

    if (t < 2) sZ[t] = 1.0f / (sDot[t][0] + sDot[t][1] + EPS_C);
    // sZ[0] read after barrier2, sZ[1] after barrier3

    #define DO_ROW(pp, ss, pr, Po, So, it, vacc)                    \
    {                                                               \
        const float kk = sK[pr][drow8 + 8 * (it)];                  \
        const float qq = sQ[pr][drow8 + 8 * (it)];                  \
        float4 pn, sn;                                              \
        pn.x = MU_C * (pp).x - kk * val4.x;                         \
        pn.y = MU_C * (pp).y - kk * val4.y;                         \
        pn.z = MU_C * (pp).z - kk * val4.z;                         \
        pn.w = MU_C * (pp).w - kk * val4.w;                         \
        sn.x = (ss).x - pn.x;                                       \
        sn.y = (ss).y - pn.y;                                       \
        sn.z = (ss).z - pn.z;                                       \
        sn.w = (ss).w - pn.w;                                       \
        __stcs(Po + ob + (it) * 128, pn);                           \
        __stcs(So + ob + (it) * 128, sn);                           \
        vacc.x += qq * sn.x;                                        \
        vacc.y += qq * sn.y;                                        \
        vacc.z += qq * sn.z;                                        \
        vacc.w += qq * sn.w;                                        \
    }

    // ---- pair0 compute + store burst ----
    {
        const float4 val4 = ((const float4*)sVal[0])[g];
        float4 vacc = make_float4(0.f, 0.f, 0.f, 0.f);
        DO_ROW(p0, s0, 0, Po4_0, So4_0, 0, vacc)
        DO_ROW(p1, s1, 0, Po4_0, So4_0, 1, vacc)
        DO_ROW(p2, s2, 0, Po4_0, So4_0, 2, vacc)
        DO_ROW(p3, s3, 0, Po4_0, So4_0, 3, vacc)
        DO_ROW(p4, s4, 0, Po4_0, So4_0, 4, vacc)
        DO_ROW(p5, s5, 0, Po4_0, So4_0, 5, vacc)
        DO_ROW(p6, s6, 0, Po4_0, So4_0, 6, vacc)
        DO_ROW(p7, s7, 0, Po4_0, So4_0, 7, vacc)
        sAcc[0][t] = vacc;
    }

    // ---- pair1 loads: issued BEFORE pair0's epilogue (pair0 regs now dead) ----
    p0 = __ldcs(Pi4_1 + ob + 0 * 128);
    p1 = __ldcs(Pi4_1 + ob + 1 * 128);
    p2 = __ldcs(Pi4_1 + ob + 2 * 128);
    p3 = __ldcs(Pi4_1 + ob + 3 * 128);
    p4 = __ldcs(Pi4_1 + ob + 4 * 128);
    p5 = __ldcs(Pi4_1 + ob + 5 * 128);
    p6 = __ldcs(Pi4_1 + ob + 6 * 128);
    p7 = __ldcs(Pi4_1 + ob + 7 * 128);
    s0 = __ldcs(Si4_1 + ob + 0 * 128);
    s1 = __ldcs(Si4_1 + ob + 1 * 128);
    s2 = __ldcs(Si4_1 + ob + 2 * 128);
    s3 = __ldcs(Si4_1 + ob + 3 * 128);
    s4 = __ldcs(Si4_1 + ob + 4 * 128);
    s5 = __ldcs(Si4_1 + ob + 5 * 128);
    s6 = __ldcs(Si4_1 + ob + 6 * 128);
    s7 = __ldcs(Si4_1 + ob + 7 * 128);

    __syncthreads();

    // ---- pair0 V readout (overlaps pair1 loads in flight) ----
    if (t < MM) {
        const int gg = t >> 2;
        const int c  = t & 3;
        const float* accf = (const float*)sAcc[0];
        float sum = 0.f;
        #pragma unroll
        for (int r = 0; r < 8; ++r)
            sum += accf[(r * 16 + gg) * 4 + c];
        Vout[base64_0 + t] = sum * sZ[0];
    }

    // ---- pair1 compute + store burst ----
    {
        const float4 val4 = ((const float4*)sVal[1])[g];
        float4 vacc = make_float4(0.f, 0.f, 0.f, 0.f);
        DO_ROW(p0, s0, 1, Po4_1, So4_1, 0, vacc)
        DO_ROW(p1, s1, 1, Po4_1, So4_1, 1, vacc)
        DO_ROW(p2, s2, 1, Po4_1, So4_1, 2, vacc)
        DO_ROW(p3, s3, 1, Po4_1, So4_1, 3, vacc)
        DO_ROW(p4, s4, 1, Po4_1, So4_1, 4, vacc)
        DO_ROW(p5, s5, 1, Po4_1, So4_1, 5, vacc)
        DO_ROW(p6, s6, 1, Po4_1, So4_1, 6, vacc)
        DO_ROW(p7, s7, 1, Po4_1, So4_1, 7, vacc)
        sAcc[1][t] = vacc;
    }
    #undef DO_ROW

    __syncthreads();

    // ---- pair1 V readout ----
    if (t < MM) {
        const int gg = t >> 2;
        const int c  = t & 3;
        const float* accf = (const float*)sAcc[1];
        float sum = 0.f;
        #pragma unroll
        for (int r = 0; r < 8; ++r)
            sum += accf[(r * 16 + gg) * 4 + c];
        Vout[base64_1 + t] = sum * sZ[1];
    }
}

extern "C" void kernel_launch(void* const* d_in, const int* in_sizes, int n_in,
                              void* d_out, int out_size) {
    // metadata order: query, key, value, Si, Zi, Pi
    const float* q  = (const float*)d_in[0];
    const float* k  = (const float*)d_in[1];
    const float* v  = (const float*)d_in[2];
    const float* Si = (const float*)d_in[3];
    const float* Zi = (const float*)d_in[4];
    const float* Pi = (const float*)d_in[5];

    float* out = (float*)d_out;
    // reference returns (V, Si_new, Zi_new, Pi_new) -> concatenated flat
    float* Vout = out;
    float* Sout = Vout + (size_t)NN * HH * MM;
    float* Zout = Sout + (size_t)NN * HH * DD * MM;
    float* Pout = Zout + (size_t)NN * HH * DD;

    rma_kernel<<<NB / 2, 128>>>(q, k, v, Si, Zi, Pi, Vout, Sout, Zout, Pout);
}

// round 9
// speedup vs baseline: 1.0249x; 1.0249x over previous
#include <cuda_runtime.h>
#include <cuda_bf16.h>

#define NN 1024
#define HH 16
#define DD 64
#define MM 64
#define NB (NN * HH)          // 16384 independent (n,h) pairs

static constexpr float MU_C  = 0.9f;
static constexpr float EPS_C = 1e-6f;

// R7 structure (best: 128 thr, 16-deep front-batched loads, one pair/CTA),
// single change: stores are grouped by REGION. All 8 Pi_new stores issue as
// one contiguous burst to Po (16KB/CTA), then all 8 Si_new stores to So.
// R7 alternated Po/So per row, ping-ponging DRAM pages between two buffers
// 512MB apart at 512B granularity; grouping doubles the per-region burst.
__global__ __launch_bounds__(128, 5)
void rma_kernel(const float* __restrict__ q_in,
                const float* __restrict__ k_in,
                const float* __restrict__ v_in,
                const float* __restrict__ Si_in,
                const float* __restrict__ Zi_in,
                const float* __restrict__ Pi_in,
                float* __restrict__ Vout,
                float* __restrict__ Sout,
                float* __restrict__ Zout,
                float* __restrict__ Pout)
{
    const int b = blockIdx.x;
    const int t = threadIdx.x;         // 0..127

    __shared__ float  sQ[DD];
    __shared__ float  sK[DD];
    __shared__ float  sVal[MM];
    __shared__ float  sDotPart[2];
    __shared__ float  sZ;
    __shared__ float4 sAcc[128];

    const int base64   = b * 64;
    const int base4096 = b * 4096;

    const int g     = t & 15;          // float4 column group
    const int drow8 = t >> 4;          // 0..7

    const float4* __restrict__ Pi4 = (const float4*)(Pi_in + base4096);
    const float4* __restrict__ Si4 = (const float4*)(Si_in + base4096);

    const int ob = drow8 * 16 + g;     // row it adds 128 float4 (2048B)

    // ---- 16 front-batched loads (evict-first): Pi burst then Si burst ----
    float4 p0 = __ldcs(Pi4 + ob + 0 * 128);
    float4 p1 = __ldcs(Pi4 + ob + 1 * 128);
    float4 p2 = __ldcs(Pi4 + ob + 2 * 128);
    float4 p3 = __ldcs(Pi4 + ob + 3 * 128);
    float4 p4 = __ldcs(Pi4 + ob + 4 * 128);
    float4 p5 = __ldcs(Pi4 + ob + 5 * 128);
    float4 p6 = __ldcs(Pi4 + ob + 6 * 128);
    float4 p7 = __ldcs(Pi4 + ob + 7 * 128);
    float4 s0 = __ldcs(Si4 + ob + 0 * 128);
    float4 s1 = __ldcs(Si4 + ob + 1 * 128);
    float4 s2 = __ldcs(Si4 + ob + 2 * 128);
    float4 s3 = __ldcs(Si4 + ob + 3 * 128);
    float4 s4 = __ldcs(Si4 + ob + 4 * 128);
    float4 s5 = __ldcs(Si4 + ob + 5 * 128);
    float4 s6 = __ldcs(Si4 + ob + 6 * 128);
    float4 s7 = __ldcs(Si4 + ob + 7 * 128);

    // ---- small vectors: featurize, Zi update, partial dot (overlaps loads) ----
    if (t < DD) {
        float xq = q_in[base64 + t];
        float fq = (xq > 0.f) ? (xq + 1.f) : __expf(xq);   // elu(x)+1
        sQ[t] = fq;

        float xk = k_in[base64 + t];
        float fk = (xk > 0.f) ? (xk + 1.f) : __expf(xk);
        sK[t] = fk;

        float zn = Zi_in[base64 + t] + fk;
        Zout[base64 + t] = zn;

        float d = fq * zn;
        #pragma unroll
        for (int off = 16; off > 0; off >>= 1)
            d += __shfl_down_sync(0xffffffffu, d, off);
        if ((t & 31) == 0) sDotPart[t >> 5] = d;
    } else {
        sVal[t - 64] = v_in[base64 + (t - 64)];
    }
    __syncthreads();

    if (t == 0) sZ = 1.0f / (sDotPart[0] + sDotPart[1] + EPS_C);
    // (sZ only read after the second __syncthreads)

    const float4 val4 = ((const float4*)sVal)[g];

    float4* __restrict__ Po4 = (float4*)(Pout + base4096);
    float4* __restrict__ So4 = (float4*)(Sout + base4096);

    // ---- phase 1: pn for all rows (in place over p), Po store burst ----
    #define MK_PN(pp, it)                                           \
    {                                                               \
        const float kk = sK[drow8 + 8 * (it)];                      \
        (pp).x = MU_C * (pp).x - kk * val4.x;                       \
        (pp).y = MU_C * (pp).y - kk * val4.y;                       \
        (pp).z = MU_C * (pp).z - kk * val4.z;                       \
        (pp).w = MU_C * (pp).w - kk * val4.w;                       \
    }
    MK_PN(p0, 0) MK_PN(p1, 1) MK_PN(p2, 2) MK_PN(p3, 3)
    MK_PN(p4, 4) MK_PN(p5, 5) MK_PN(p6, 6) MK_PN(p7, 7)
    #undef MK_PN

    __stcs(Po4 + ob + 0 * 128, p0);
    __stcs(Po4 + ob + 1 * 128, p1);
    __stcs(Po4 + ob + 2 * 128, p2);
    __stcs(Po4 + ob + 3 * 128, p3);
    __stcs(Po4 + ob + 4 * 128, p4);
    __stcs(Po4 + ob + 5 * 128, p5);
    __stcs(Po4 + ob + 6 * 128, p6);
    __stcs(Po4 + ob + 7 * 128, p7);

    // ---- phase 2: sn = s - pn (in place over s), So store burst + vacc ----
    float4 vacc = make_float4(0.f, 0.f, 0.f, 0.f);

    #define MK_SN(ss, pp, it)                                       \
    {                                                               \
        const float qq = sQ[drow8 + 8 * (it)];                      \
        (ss).x -= (pp).x;                                           \
        (ss).y -= (pp).y;                                           \
        (ss).z -= (pp).z;                                           \
        (ss).w -= (pp).w;                                           \
        __stcs(So4 + ob + (it) * 128, (ss));                        \
        vacc.x += qq * (ss).x;                                      \
        vacc.y += qq * (ss).y;                                      \
        vacc.z += qq * (ss).z;                                      \
        vacc.w += qq * (ss).w;                                      \
    }
    MK_SN(s0, p0, 0) MK_SN(s1, p1, 1) MK_SN(s2, p2, 2) MK_SN(s3, p3, 3)
    MK_SN(s4, p4, 4) MK_SN(s5, p5, 5) MK_SN(s6, p6, 6) MK_SN(s7, p7, 7)
    #undef MK_SN

    sAcc[t] = vacc;
    __syncthreads();

    // ---- V readout: reduce 8 row-octet partials per m, scale by Z ----
    if (t < MM) {
        const int gg = t >> 2;
        const int c  = t & 3;
        const float* accf = (const float*)sAcc;
        float sum = 0.f;
        #pragma unroll
        for (int r = 0; r < 8; ++r)
            sum += accf[(r * 16 + gg) * 4 + c];
        Vout[base64 + t] = sum * sZ;
    }
}

extern "C" void kernel_launch(void* const* d_in, const int* in_sizes, int n_in,
                              void* d_out, int out_size) {
    // metadata order: query, key, value, Si, Zi, Pi
    const float* q  = (const float*)d_in[0];
    const float* k  = (const float*)d_in[1];
    const float* v  = (const float*)d_in[2];
    const float* Si = (const float*)d_in[3];
    const float* Zi = (const float*)d_in[4];
    const float* Pi = (const float*)d_in[5];

    float* out = (float*)d_out;
    // reference returns (V, Si_new, Zi_new, Pi_new) -> concatenated flat
    float* Vout = out;
    float* Sout = Vout + (size_t)NN * HH * MM;
    float* Zout = Sout + (size_t)NN * HH * DD * MM;
    float* Pout = Zout + (size_t)NN * HH * DD;

    rma_kernel<<<NB, 128>>>(q, k, v, Si, Zi, Pi, Vout, Sout, Zout, Pout);
}

// round 10
// speedup vs baseline: 1.0314x; 1.0064x over previous
#include <cuda_runtime.h>
#include <cuda_bf16.h>

#define NN 1024
#define HH 16
#define DD 64
#define MM 64
#define NB (NN * HH)          // 16384 independent (n,h) pairs

static constexpr float MU_C  = 0.9f;
static constexpr float EPS_C = 1e-6f;

// R9 body (region-grouped stores, 87 regs) with occupancy raised to 6 CTAs/SM
// (85-reg cap): 24 warps/SM x 16-deep front-batched loads = 192KB potential
// in-flight vs R7's 152KB. Tests the last unexplored corner of the
// (warps x batch-depth) space.
__global__ __launch_bounds__(128, 6)
void rma_kernel(const float* __restrict__ q_in,
                const float* __restrict__ k_in,
                const float* __restrict__ v_in,
                const float* __restrict__ Si_in,
                const float* __restrict__ Zi_in,
                const float* __restrict__ Pi_in,
                float* __restrict__ Vout,
                float* __restrict__ Sout,
                float* __restrict__ Zout,
                float* __restrict__ Pout)
{
    const int b = blockIdx.x;
    const int t = threadIdx.x;         // 0..127

    __shared__ float  sQ[DD];
    __shared__ float  sK[DD];
    __shared__ float  sVal[MM];
    __shared__ float  sDotPart[2];
    __shared__ float  sZ;
    __shared__ float4 sAcc[128];

    const int base64   = b * 64;
    const int base4096 = b * 4096;

    const int g     = t & 15;          // float4 column group
    const int drow8 = t >> 4;          // 0..7

    const float4* __restrict__ Pi4 = (const float4*)(Pi_in + base4096);
    const float4* __restrict__ Si4 = (const float4*)(Si_in + base4096);

    const int ob = drow8 * 16 + g;     // row it adds 128 float4 (2048B)

    // ---- 16 front-batched loads (evict-first): Pi burst then Si burst ----
    float4 p0 = __ldcs(Pi4 + ob + 0 * 128);
    float4 p1 = __ldcs(Pi4 + ob + 1 * 128);
    float4 p2 = __ldcs(Pi4 + ob + 2 * 128);
    float4 p3 = __ldcs(Pi4 + ob + 3 * 128);
    float4 p4 = __ldcs(Pi4 + ob + 4 * 128);
    float4 p5 = __ldcs(Pi4 + ob + 5 * 128);
    float4 p6 = __ldcs(Pi4 + ob + 6 * 128);
    float4 p7 = __ldcs(Pi4 + ob + 7 * 128);
    float4 s0 = __ldcs(Si4 + ob + 0 * 128);
    float4 s1 = __ldcs(Si4 + ob + 1 * 128);
    float4 s2 = __ldcs(Si4 + ob + 2 * 128);
    float4 s3 = __ldcs(Si4 + ob + 3 * 128);
    float4 s4 = __ldcs(Si4 + ob + 4 * 128);
    float4 s5 = __ldcs(Si4 + ob + 5 * 128);
    float4 s6 = __ldcs(Si4 + ob + 6 * 128);
    float4 s7 = __ldcs(Si4 + ob + 7 * 128);

    // ---- small vectors: featurize, Zi update, partial dot (overlaps loads) ----
    if (t < DD) {
        float xq = q_in[base64 + t];
        float fq = (xq > 0.f) ? (xq + 1.f) : __expf(xq);   // elu(x)+1
        sQ[t] = fq;

        float xk = k_in[base64 + t];
        float fk = (xk > 0.f) ? (xk + 1.f) : __expf(xk);
        sK[t] = fk;

        float zn = Zi_in[base64 + t] + fk;
        Zout[base64 + t] = zn;

        float d = fq * zn;
        #pragma unroll
        for (int off = 16; off > 0; off >>= 1)
            d += __shfl_down_sync(0xffffffffu, d, off);
        if ((t & 31) == 0) sDotPart[t >> 5] = d;
    } else {
        sVal[t - 64] = v_in[base64 + (t - 64)];
    }
    __syncthreads();

    if (t == 0) sZ = 1.0f / (sDotPart[0] + sDotPart[1] + EPS_C);
    // (sZ only read after the second __syncthreads)

    const float4 val4 = ((const float4*)sVal)[g];

    float4* __restrict__ Po4 = (float4*)(Pout + base4096);
    float4* __restrict__ So4 = (float4*)(Sout + base4096);

    // ---- phase 1: pn for all rows (in place over p), Po store burst ----
    #define MK_PN(pp, it)                                           \
    {                                                               \
        const float kk = sK[drow8 + 8 * (it)];                      \
        (pp).x = MU_C * (pp).x - kk * val4.x;                       \
        (pp).y = MU_C * (pp).y - kk * val4.y;                       \
        (pp).z = MU_C * (pp).z - kk * val4.z;                       \
        (pp).w = MU_C * (pp).w - kk * val4.w;                       \
    }
    MK_PN(p0, 0) MK_PN(p1, 1) MK_PN(p2, 2) MK_PN(p3, 3)
    MK_PN(p4, 4) MK_PN(p5, 5) MK_PN(p6, 6) MK_PN(p7, 7)
    #undef MK_PN

    __stcs(Po4 + ob + 0 * 128, p0);
    __stcs(Po4 + ob + 1 * 128, p1);
    __stcs(Po4 + ob + 2 * 128, p2);
    __stcs(Po4 + ob + 3 * 128, p3);
    __stcs(Po4 + ob + 4 * 128, p4);
    __stcs(Po4 + ob + 5 * 128, p5);
    __stcs(Po4 + ob + 6 * 128, p6);
    __stcs(Po4 + ob + 7 * 128, p7);

    // ---- phase 2: sn = s - pn (in place over s), So store burst + vacc ----
    float4 vacc = make_float4(0.f, 0.f, 0.f, 0.f);

    #define MK_SN(ss, pp, it)                                       \
    {                                                               \
        const float qq = sQ[drow8 + 8 * (it)];                      \
        (ss).x -= (pp).x;                                           \
        (ss).y -= (pp).y;                                           \
        (ss).z -= (pp).z;                                           \
        (ss).w -= (pp).w;                                           \
        __stcs(So4 + ob + (it) * 128, (ss));                        \
        vacc.x += qq * (ss).x;                                      \
        vacc.y += qq * (ss).y;                                      \
        vacc.z += qq * (ss).z;                                      \
        vacc.w += qq * (ss).w;                                      \
    }
    MK_SN(s0, p0, 0) MK_SN(s1, p1, 1) MK_SN(s2, p2, 2) MK_SN(s3, p3, 3)
    MK_SN(s4, p4, 4) MK_SN(s5, p5, 5) MK_SN(s6, p6, 6) MK_SN(s7, p7, 7)
    #undef MK_SN

    sAcc[t] = vacc;
    __syncthreads();

    // ---- V readout: reduce 8 row-octet partials per m, scale by Z ----
    if (t < MM) {
        const int gg = t >> 2;
        const int c  = t & 3;
        const float* accf = (const float*)sAcc;
        float sum = 0.f;
        #pragma unroll
        for (int r = 0; r < 8; ++r)
            sum += accf[(r * 16 + gg) * 4 + c];
        Vout[base64 + t] = sum * sZ;
    }
}

extern "C" void kernel_launch(void* const* d_in, const int* in_sizes, int n_in,
                              void* d_out, int out_size) {
    // metadata order: query, key, value, Si, Zi, Pi
    const float* q  = (const float*)d_in[0];
    const float* k  = (const float*)d_in[1];
    const float* v  = (const float*)d_in[2];
    const float* Si = (const float*)d_in[3];
    const float* Zi = (const float*)d_in[4];
    const float* Pi = (const float*)d_in[5];

    float* out = (float*)d_out;
    // reference returns (V, Si_new, Zi_new, Pi_new) -> concatenated flat
    float* Vout = out;
    float* Sout = Vout + (size_t)NN * HH * MM;
    float* Zout = Sout + (size_t)NN * HH * DD * MM;
    float* Pout = Zout + (size_t)NN * HH * DD;

    rma_kernel<<<NB, 128>>>(q, k, v, Si, Zi, Pi, Vout, Sout, Zout, Pout);
}